// round 12
// baseline (speedup 1.0000x reference)
#include <cuda_runtime.h>

// Problem constants
//   x  : [B=8, Ci=32, T=128, X=256, P=3]  float32
//   w* : [Ci=32, Co=32, M1=16, M2=16, M3=3] float32
//   out: [B=8, Co=32, T=128, X=256, P=3]  float32
//
// Active spectral modes: kt in {0..15} (w1) and {112..127} (w2),
// kx in {0..15}, kz in {0,1}. lane = kx*2 + z packs the 32 (kx,z) pairs.

#define SQ3H 0.8660254037844386f // sqrt(3)/2

typedef unsigned long long u64;

// ---- packed f32x2 helpers (FFMA2 path) ------------------------------------
__device__ __forceinline__ u64 pk2(float lo, float hi) {
    u64 r; asm("mov.b64 %0, {%1, %2};" : "=l"(r) : "f"(lo), "f"(hi)); return r;
}
__device__ __forceinline__ void up2(u64 v, float& lo, float& hi) {
    asm("mov.b64 {%0, %1}, %2;" : "=f"(lo), "=f"(hi) : "l"(v));
}
__device__ __forceinline__ u64 fma2(u64 a, u64 b, u64 c) {
    u64 d; asm("fma.rn.f32x2 %0, %1, %2, %3;" : "=l"(d) : "l"(a), "l"(b), "l"(c)); return d;
}

// Scratch (device globals; allocation is banned)
static __device__ float2 g_Y[8 * 32 * 128 * 32]; // [b][ci][t][lane]   8 MB
static __device__ float2 g_Z[8 * 32 * 32 * 32];  // [b][ci][kt][lane]  2 MB
static __device__ float2 g_H[8 * 32 * 32 * 32];  // [b][co][kt][lane]  2 MB
static __device__ float2 g_A[8 * 32 * 128 * 32]; // [b][co][t][lane]   8 MB

// twiddle tables
// dup-packed (c,c,s,s):
static __device__ float4 g_Tf[32 * 128]; // fwd t: [kt][t]  e^{-2pi i freq(kt) t/128}
static __device__ float4 g_Ti[64 * 32];  // inv t: [t][kt]  e^{+2pi i freq(kt) t/128}
// quadrature-packed (c,s,s,c):
static __device__ float4 g_Tx[64 * 16];  // fwd x: [xp][kx] e^{-2pi i kx xp/256}
static __device__ float4 g_T5[16 * 64];  // inv x: [k][x0]  e^{+2pi i k x0/256}

// ---------------------------------------------------------------------------
// K0: build twiddle tables (tiny; runs every launch, deterministic)
// ---------------------------------------------------------------------------
__global__ void k_tw() {
    int i = blockIdx.x * 256 + threadIdx.x;
    if (i < 4096) {
        int kt = i >> 7, t = i & 127;
        int f = (kt < 16) ? kt : 96 + kt;
        float s, c; sincospif(-(float)(f * t) / 64.0f, &s, &c);
        g_Tf[i] = make_float4(c, c, s, s);
    } else if (i < 6144) {
        int j = i - 4096; int t = j >> 5, kt = j & 31;
        int f = (kt < 16) ? kt : 96 + kt;
        float s, c; sincospif((float)(f * t) / 64.0f, &s, &c);
        g_Ti[j] = make_float4(c, c, s, s);
    } else if (i < 7168) {
        int j = i - 6144; int xp = j >> 4, kx = j & 15;
        float s, c; sincospif(-(float)(kx * xp) / 128.0f, &s, &c);
        g_Tx[j] = make_float4(c, s, s, c);
    } else if (i < 8192) {
        int j = i - 7168; int k = j >> 6, x0 = j & 63;
        float s, c; sincospif((float)(k * x0) / 128.0f, &s, &c);
        g_T5[j] = make_float4(c, s, s, c);
    }
}

// ---------------------------------------------------------------------------
// K1: forward p-rfft + x-DFT, lane-parallel with radix-4 DIF over x.
// Block = 8 rows. Phase 1: per x0<64, combine x0,x0+64,x0+128,x0+192 into the
// four k-mod-4 classes for both the f0 and f1 channels.
// Phase 2: warp per row; lane = (kx,z); table twiddles, quadrature accum:
// per iter just 1 LDS.64 + 1 LDG.128 + 2 FFMA2. No chain, no shfl.
// ---------------------------------------------------------------------------
__global__ __launch_bounds__(256) void k_fwd_x(const float* __restrict__ x) {
    __shared__ __align__(16) float2 sD[8][64][8]; // 32 KB
    int row0 = blockIdx.x * 8;
    int tid = threadIdx.x;

#pragma unroll
    for (int tsk = 0; tsk < 2; tsk++) {
        int task = tid + 256 * tsk; // 0..511
        int rl = task >> 6;
        int x0 = task & 63;
        const float* xp = x + (size_t)(row0 + rl) * 768 + 3 * x0;
        float f0[4], f1r[4], f1i[4];
#pragma unroll
        for (int j = 0; j < 4; j++) {
            float a = xp[192 * j + 0], b = xp[192 * j + 1], c = xp[192 * j + 2];
            float s = b + c;
            f0[j]  = a + s;
            f1r[j] = fmaf(-0.5f, s, a);
            f1i[j] = SQ3H * (c - b);
        }
        float s02 = f0[0] + f0[2], s13 = f0[1] + f0[3];
        float p0 = f0[0] - f0[2], m0 = f0[1] - f0[3];
        float r02 = f1r[0] + f1r[2], r13 = f1r[1] + f1r[3];
        float i02 = f1i[0] + f1i[2], i13 = f1i[1] + f1i[3];
        float pr = f1r[0] - f1r[2], mr = f1r[1] - f1r[3];
        float pi = f1i[0] - f1i[2], mi = f1i[1] - f1i[3];
        float2* d = sD[rl][x0];
        d[0] = make_float2(s02 + s13, 0.0f);      // class 0, f0
        d[1] = make_float2(p0, -m0);              // class 1, f0 : P - iM
        d[2] = make_float2(s02 - s13, 0.0f);      // class 2, f0
        d[3] = make_float2(p0, m0);               // class 3, f0 : P + iM
        d[4] = make_float2(r02 + r13, i02 + i13); // class 0, f1
        d[5] = make_float2(pr + mi, pi - mr);     // class 1, f1 : Pc - i Mc
        d[6] = make_float2(r02 - r13, i02 - i13); // class 2, f1
        d[7] = make_float2(pr - mi, pi + mr);     // class 3, f1 : Pc + i Mc
    }
    __syncthreads();

    int warp = tid >> 5, lane = tid & 31;
    int kx = lane >> 1, z = lane & 1;
    int slot = (z << 2) | (kx & 3);

    u64 U = 0ull, V = 0ull;
    const u64* dp = reinterpret_cast<const u64*>(&sD[warp][0][slot]);
    const ulonglong2* Tp = reinterpret_cast<const ulonglong2*>(g_Tx) + kx;
#pragma unroll 16
    for (int xp = 0; xp < 64; xp++) {
        u64 v = dp[xp * 8];
        ulonglong2 w = Tp[xp * 16]; // w.x=(c,s) w.y=(s,c), angle -2pi kx xp/256
        U = fma2(v, w.x, U);        // (vr*c, vi*s)
        V = fma2(v, w.y, V);        // (vr*s, vi*c)
    }
    float ua, ub, va, vb; up2(U, ua, ub); up2(V, va, vb);
    g_Y[(size_t)(row0 + warp) * 32 + lane] = make_float2(ua - ub, va + vb);
}

// ---------------------------------------------------------------------------
// K2: forward t-DFT: 128 t -> 32 kt. Warp per (b,ci,kt); packed + table.
// ---------------------------------------------------------------------------
__global__ __launch_bounds__(256) void k_fwd_t() {
    int g    = (blockIdx.x * 256 + threadIdx.x) >> 5; // 0..8191
    int lane = threadIdx.x & 31;
    int kt = g & 31, ci = (g >> 5) & 31, b = g >> 10;

    const u64* Yp = reinterpret_cast<const u64*>(g_Y) + (size_t)(b * 32 + ci) * 4096 + lane;
    const ulonglong2* T = reinterpret_cast<const ulonglong2*>(g_Tf) + kt * 128;
    u64 U = 0ull, V = 0ull;
#pragma unroll 8
    for (int t = 0; t < 128; t++) {
        u64 v = Yp[(size_t)t * 32];
        ulonglong2 w = T[t]; // (wr,wr | wi,wi), uniform across warp
        U = fma2(v, w.x, U);
        V = fma2(v, w.y, V);
    }
    float ua, ub, va, vb; up2(U, ua, ub); up2(V, va, vb);
    g_Z[((size_t)(b * 32 + ci) * 32 + kt) * 32 + lane] = make_float2(ua - vb, va + ub);
}

// ---------------------------------------------------------------------------
// K3: channel mix: H = sum_ci Z * w  (w1 for kt<16 j=kt, w2 for kt>=16 j=kt-16)
// Deep unroll for MLP (latency-bound per ncu: issue 32.5%).
// ---------------------------------------------------------------------------
__global__ __launch_bounds__(256) void k_mix(const float* __restrict__ w1r,
                                             const float* __restrict__ w1i,
                                             const float* __restrict__ w2r,
                                             const float* __restrict__ w2i) {
    int idx  = blockIdx.x * 256 + threadIdx.x; // H linear index
    int lane = idx & 31;
    int kt   = (idx >> 5) & 31;
    int co   = (idx >> 10) & 31;
    int b    = idx >> 15;
    int kx = lane >> 1, z = lane & 1;

    const float* wr = (kt < 16) ? w1r : w2r;
    const float* wi = (kt < 16) ? w1i : w2i;
    int j     = kt & 15;
    int wbase = co * 768 + j * 48 + kx * 3 + z;

    float ar = 0.0f, ai = 0.0f;
    const float2* Zp = g_Z + (size_t)b * 32768 + (size_t)kt * 32 + lane;
#pragma unroll 8
    for (int ci = 0; ci < 32; ci++) {
        float2 zv = __ldg(Zp + ci * 1024);
        float  wre = __ldg(wr + wbase + ci * 24576);
        float  wim = __ldg(wi + wbase + ci * 24576);
        ar = fmaf(zv.x, wre, ar); ar = fmaf(-zv.y, wim, ar);
        ai = fmaf(zv.x, wim, ai); ai = fmaf(zv.y, wre, ai);
    }
    g_H[idx] = make_float2(ar, ai);
}

// ---------------------------------------------------------------------------
// K4: inverse t-DFT with t / t+64 parity symmetry. Warp per (b,co,t0<64).
// ---------------------------------------------------------------------------
__global__ __launch_bounds__(256) void k_inv_t() {
    int g    = (blockIdx.x * 256 + threadIdx.x) >> 5; // 0..16383
    int lane = threadIdx.x & 31;
    int t0 = g & 63, co = (g >> 6) & 31, b = g >> 11;

    const u64* Hp = reinterpret_cast<const u64*>(g_H) + (size_t)(b * 32 + co) * 1024 + lane;
    const ulonglong2* T = reinterpret_cast<const ulonglong2*>(g_Ti) + t0 * 32;
    u64 U0 = 0ull, V0 = 0ull, U1 = 0ull, V1 = 0ull;
#pragma unroll
    for (int kt = 0; kt < 32; kt += 2) {
        u64 v0 = Hp[(size_t)kt * 32];
        ulonglong2 w0 = T[kt];
        U0 = fma2(v0, w0.x, U0); V0 = fma2(v0, w0.y, V0);
        u64 v1 = Hp[(size_t)(kt + 1) * 32];
        ulonglong2 w1 = T[kt + 1];
        U1 = fma2(v1, w1.x, U1); V1 = fma2(v1, w1.y, V1);
    }
    float a, bb, c, d;
    up2(U0, a, bb); up2(V0, c, d); float er = a - d, ei = c + bb;
    up2(U1, a, bb); up2(V1, c, d); float orr = a - d, oi = c + bb;
    size_t base = (size_t)(b * 32 + co) * 128;
    g_A[(base + t0) * 32 + lane]      = make_float2(er + orr, ei + oi);
    g_A[(base + t0 + 64) * 32 + lane] = make_float2(er - orr, ei - oi);
}

// ---------------------------------------------------------------------------
// K5: inverse x-DFT + irfft(p=3) + store. Thread = x0<64; radix-4 group
// accumulators -> outputs at x0, x0+64, x0+128, x0+192. Table twiddles,
// quadrature accumulation (4 FFMA2 + 1 LDG.128 + 1 LDS.128 per mode).
// ---------------------------------------------------------------------------
__global__ __launch_bounds__(256) void k_inv_x(float* __restrict__ out) {
    __shared__ __align__(16) float2 sA[128]; // 4 rows x 32 coeffs
    int tid = threadIdx.x;
    size_t row0 = (size_t)blockIdx.x * 4;
    if (tid < 128) sA[tid] = g_A[row0 * 32 + tid];
    __syncthreads();

    int rl = tid >> 6, x0 = tid & 63;
    const ulonglong2* Ap = reinterpret_cast<const ulonglong2*>(sA) + rl * 16;
    const ulonglong2* Tp = reinterpret_cast<const ulonglong2*>(g_T5) + x0;

    u64 U0[4] = {0,0,0,0}, V0[4] = {0,0,0,0}, U1[4] = {0,0,0,0}, V1[4] = {0,0,0,0};
#pragma unroll
    for (int k = 0; k < 16; k++) {
        ulonglong2 q = Ap[k];       // (a0 | a1) for this kx
        ulonglong2 w = Tp[k * 64];  // (c,s | s,c), angle +2pi k x0/256
        int gI = k & 3;
        U0[gI] = fma2(q.x, w.x, U0[gI]); V0[gI] = fma2(q.x, w.y, V0[gI]);
        U1[gI] = fma2(q.y, w.x, U1[gI]); V1[gI] = fma2(q.y, w.y, V1[gI]);
    }
    float S0r[4], S0i[4], S1r[4], S1i[4];
#pragma unroll
    for (int gi = 0; gi < 4; gi++) {
        float a, b2, c, d;
        up2(U0[gi], a, b2); up2(V0[gi], c, d); S0r[gi] = a - b2; S0i[gi] = c + d;
        up2(U1[gi], a, b2); up2(V1[gi], c, d); S1r[gi] = a - b2; S1i[gi] = c + d;
    }
    // radix-4 butterflies: S(d) = T0+T2 | T1+iT3 | T0-T2 | T1-iT3
    float T0r = S0r[0] + S0r[2], T1r = S0r[0] - S0r[2];
    float T2r = S0r[1] + S0r[3], T3r = S0r[1] - S0r[3];
    float T3i = S0i[1] - S0i[3];
    float U0r = S1r[0] + S1r[2], U1r = S1r[0] - S1r[2];
    float U2r = S1r[1] + S1r[3], U3r = S1r[1] - S1r[3];
    float U0i = S1i[0] + S1i[2], U1i = S1i[0] - S1i[2];
    float U2i = S1i[1] + S1i[3], U3i = S1i[1] - S1i[3];
    (void)T3r;

    float s0[4], s1r_[4], s1i_[4];
    s0[0] = T0r + T2r; s1r_[0] = U0r + U2r; s1i_[0] = U0i + U2i; // d=0
    s0[1] = T1r - T3i; s1r_[1] = U1r - U3i; s1i_[1] = U1i + U3r; // d=64
    s0[2] = T0r - T2r; s1r_[2] = U0r - U2r; s1i_[2] = U0i - U2i; // d=128
    s0[3] = T1r + T3i; s1r_[3] = U1r + U3i; s1i_[3] = U1i - U3r; // d=192

    const float inv = 1.0f / 98304.0f; // 1/(T*X*P)
    size_t rbase = (row0 + rl) * 256;
#pragma unroll
    for (int dd = 0; dd < 4; dd++) {
        int xx = x0 + 64 * dd;
        float S0 = s0[dd], R = s1r_[dd], I = s1i_[dd];
        float p0 = (S0 + 2.0f * R) * inv;
        float p1 = (S0 + 2.0f * (-0.5f * R - SQ3H * I)) * inv;
        float p2 = (S0 + 2.0f * (-0.5f * R + SQ3H * I)) * inv;
        size_t o = (rbase + xx) * 3;
        out[o + 0] = p0;
        out[o + 1] = p1;
        out[o + 2] = p2;
    }
}

// ---------------------------------------------------------------------------
extern "C" void kernel_launch(void* const* d_in, const int* in_sizes, int n_in,
                              void* d_out, int out_size) {
    const float* x   = (const float*)d_in[0];
    const float* w1r = (const float*)d_in[1];
    const float* w1i = (const float*)d_in[2];
    const float* w2r = (const float*)d_in[3];
    const float* w2i = (const float*)d_in[4];
    float* out = (float*)d_out;

    k_tw<<<32, 256>>>();                         // twiddle tables
    k_fwd_x<<<4096, 256>>>(x);                   // 8 rows/block
    k_fwd_t<<<1024, 256>>>();                    // 8192 warps
    k_mix<<<1024, 256>>>(w1r, w1i, w2r, w2i);    // 262144 outputs
    k_inv_t<<<2048, 256>>>();                    // 16384 warps (parity split)
    k_inv_x<<<8192, 256>>>(out);                 // 4 rows/block
}

// round 14
// speedup vs baseline: 1.4256x; 1.4256x over previous
#include <cuda_runtime.h>

// Problem constants
//   x  : [B=8, Ci=32, T=128, X=256, P=3]  float32
//   w* : [Ci=32, Co=32, M1=16, M2=16, M3=3] float32
//   out: [B=8, Co=32, T=128, X=256, P=3]  float32
//
// Active spectral modes: kt in {0..15} (w1) and {112..127} (w2),
// kx in {0..15}, kz in {0,1}. lane = kx*2 + z packs the 32 (kx,z) pairs.

#define SQ3H 0.8660254037844386f // sqrt(3)/2

typedef unsigned long long u64;

// ---- packed f32x2 helpers (FFMA2 path) ------------------------------------
__device__ __forceinline__ u64 pk2(float lo, float hi) {
    u64 r; asm("mov.b64 %0, {%1, %2};" : "=l"(r) : "f"(lo), "f"(hi)); return r;
}
__device__ __forceinline__ void up2(u64 v, float& lo, float& hi) {
    asm("mov.b64 {%0, %1}, %2;" : "=f"(lo), "=f"(hi) : "l"(v));
}
__device__ __forceinline__ u64 fma2(u64 a, u64 b, u64 c) {
    u64 d; asm("fma.rn.f32x2 %0, %1, %2, %3;" : "=l"(d) : "l"(a), "l"(b), "l"(c)); return d;
}
__device__ __forceinline__ u64 mul2(u64 a, u64 b) {
    u64 d; asm("mul.rn.f32x2 %0, %1, %2;" : "=l"(d) : "l"(a), "l"(b)); return d;
}
// dup-packed complex twiddle chain step: w *= s  (both halves identical dups)
__device__ __forceinline__ void cstep(u64& wpp, u64& wqq, u64 spp, u64 sqq, u64 sqn) {
    u64 t1 = mul2(wqq, sqn);          // -wi*si
    u64 np = fma2(wpp, spp, t1);      // wr' = wr*sr - wi*si
    u64 t2 = mul2(wqq, spp);          //  wi*sr
    wqq    = fma2(wpp, sqq, t2);      // wi' = wr*si + wi*sr
    wpp    = np;
}

// Scratch (device globals; allocation is banned)
static __device__ __align__(16) float2 g_Y[8 * 32 * 128 * 32]; // [slab=b*32+ci][t][lane]  8 MB
static __device__ __align__(16) float2 g_Z[8 * 32 * 32 * 32];  // [b][ci][kt][lane]        2 MB
static __device__ __align__(16) float2 g_H[8 * 32 * 32 * 32];  // [slab=b*32+co][kt][lane] 2 MB
static __device__ __align__(16) float2 g_A[8 * 32 * 128 * 32]; // [b][co][t][lane]         8 MB

// twiddle tables, stored dup-packed (c,c,s,s)
static __device__ __align__(16) float4 g_Tf[32 * 128]; // fwd t: [kt][t]  e^{-2pi i f(kt) t/128}
static __device__ __align__(16) float4 g_Ti[64 * 32];  // inv t: [t][kt]  e^{+2pi i f(kt) t/128}

// ---------------------------------------------------------------------------
// K0: build twiddle tables (tiny; runs every launch, deterministic)
// ---------------------------------------------------------------------------
__global__ void k_tw() {
    int i = blockIdx.x * 256 + threadIdx.x;
    if (i < 4096) {
        int kt = i >> 7, t = i & 127;
        int f = (kt < 16) ? kt : 96 + kt;
        float s, c; sincospif(-(float)(f * t) / 64.0f, &s, &c);
        g_Tf[i] = make_float4(c, c, s, s);
    } else if (i < 6144) {
        int j = i - 4096; int t = j >> 5, kt = j & 31;
        int f = (kt < 16) ? kt : 96 + kt;
        float s, c; sincospif((float)(f * t) / 64.0f, &s, &c);
        g_Ti[j] = make_float4(c, c, s, s);
    }
}

// ---------------------------------------------------------------------------
// K1: forward p-rfft + x-DFT, lane-parallel with radix-4 DIF over x.
// (R8 chain version — known good at ~this speed; table version regressed.)
// ---------------------------------------------------------------------------
__global__ __launch_bounds__(256) void k_fwd_x(const float* __restrict__ x) {
    __shared__ __align__(16) float2 sD[8][64][8]; // 32 KB
    int row0 = blockIdx.x * 8;
    int tid = threadIdx.x;

#pragma unroll
    for (int tsk = 0; tsk < 2; tsk++) {
        int task = tid + 256 * tsk; // 0..511
        int rl = task >> 6;
        int x0 = task & 63;
        const float* xp = x + (size_t)(row0 + rl) * 768 + 3 * x0;
        float f0[4], f1r[4], f1i[4];
#pragma unroll
        for (int j = 0; j < 4; j++) {
            float a = xp[192 * j + 0], b = xp[192 * j + 1], c = xp[192 * j + 2];
            float s = b + c;
            f0[j]  = a + s;
            f1r[j] = fmaf(-0.5f, s, a);
            f1i[j] = SQ3H * (c - b);
        }
        float s02 = f0[0] + f0[2], s13 = f0[1] + f0[3];
        float p0 = f0[0] - f0[2], m0 = f0[1] - f0[3];
        float r02 = f1r[0] + f1r[2], r13 = f1r[1] + f1r[3];
        float i02 = f1i[0] + f1i[2], i13 = f1i[1] + f1i[3];
        float pr = f1r[0] - f1r[2], mr = f1r[1] - f1r[3];
        float pi = f1i[0] - f1i[2], mi = f1i[1] - f1i[3];
        float2* d = sD[rl][x0];
        d[0] = make_float2(s02 + s13, 0.0f);      // class 0, f0
        d[1] = make_float2(p0, -m0);              // class 1, f0 : P - iM
        d[2] = make_float2(s02 - s13, 0.0f);      // class 2, f0
        d[3] = make_float2(p0, m0);               // class 3, f0 : P + iM
        d[4] = make_float2(r02 + r13, i02 + i13); // class 0, f1
        d[5] = make_float2(pr + mi, pi - mr);     // class 1, f1 : Pc - i Mc
        d[6] = make_float2(r02 - r13, i02 - i13); // class 2, f1
        d[7] = make_float2(pr - mi, pi + mr);     // class 3, f1 : Pc + i Mc
    }
    __syncthreads();

    int warp = tid >> 5, lane = tid & 31;
    int kx = lane >> 1, z = lane & 1;
    int slot = (z << 2) | (kx & 3);

    float sr, si; sincospif(-(float)kx / 128.0f, &si, &sr); // e^{-2pi i kx/256}
    u64 spp = pk2(sr, sr), sqq = pk2(si, si), sqn = pk2(-si, -si);
    u64 wpp = pk2(1.0f, 1.0f), wqq = pk2(0.0f, 0.0f);
    u64 U = 0ull, V = 0ull;
    const u64* dp = reinterpret_cast<const u64*>(&sD[warp][0][slot]);
#pragma unroll 16
    for (int xp = 0; xp < 64; xp++) {
        u64 v = dp[xp * 8];
        U = fma2(v, wpp, U);
        V = fma2(v, wqq, V);
        cstep(wpp, wqq, spp, sqq, sqn);
    }
    float ua, ub, va, vb; up2(U, ua, ub); up2(V, va, vb);
    g_Y[(size_t)(row0 + warp) * 32 + lane] = make_float2(ua - vb, va + ub);
}

// ---------------------------------------------------------------------------
// K2: forward t-DFT: 128 t -> 32 kt, smem-staged (kills the 256 MB L2 storm).
// Block (128 thr) = one (b,ci) slab x one kt-quarter (8 kt). Stages the 32 KB
// Y-slab + 16 KB twiddle rows; 4 warps x 2 kt each; broadcast twiddle LDS.
// ---------------------------------------------------------------------------
__global__ __launch_bounds__(128) void k_fwd_t() {
    __shared__ __align__(16) u64    sY[4096]; // [t][lane] 32 KB
    __shared__ __align__(16) float4 sT[1024]; // [ktl][t]  16 KB
    int blk  = blockIdx.x;       // 1024 blocks
    int slab = blk >> 2;         // b*32+ci
    int kq   = blk & 3;          // kt quarter
    int tid  = threadIdx.x;

    const float4* Ys = reinterpret_cast<const float4*>(g_Y + (size_t)slab * 4096);
    float4* sY4 = reinterpret_cast<float4*>(sY);
#pragma unroll
    for (int i = tid; i < 2048; i += 128) sY4[i] = Ys[i];
    const float4* Ts = g_Tf + kq * 1024;
#pragma unroll
    for (int i = tid; i < 1024; i += 128) sT[i] = Ts[i];
    __syncthreads();

    int warp = tid >> 5, lane = tid & 31;
    int k0 = 2 * warp, k1 = 2 * warp + 1; // local kt within quarter
    const ulonglong2* T0 = reinterpret_cast<const ulonglong2*>(sT + k0 * 128);
    const ulonglong2* T1 = reinterpret_cast<const ulonglong2*>(sT + k1 * 128);
    u64 U0 = 0ull, V0 = 0ull, U1 = 0ull, V1 = 0ull;
#pragma unroll 8
    for (int t = 0; t < 128; t++) {
        u64 v = sY[t * 32 + lane];
        ulonglong2 w0 = T0[t]; // (c,c | s,s), broadcast
        U0 = fma2(v, w0.x, U0); V0 = fma2(v, w0.y, V0);
        ulonglong2 w1 = T1[t];
        U1 = fma2(v, w1.x, U1); V1 = fma2(v, w1.y, V1);
    }
    float a, b2, c, d;
    up2(U0, a, b2); up2(V0, c, d);
    g_Z[((size_t)slab * 32 + kq * 8 + k0) * 32 + lane] = make_float2(a - d, c + b2);
    up2(U1, a, b2); up2(V1, c, d);
    g_Z[((size_t)slab * 32 + kq * 8 + k1) * 32 + lane] = make_float2(a - d, c + b2);
}

// ---------------------------------------------------------------------------
// K3: channel mix, reuse-tiled. Grid = kt(32) x co-group(4) x b-half(2).
// Block 256 thr = 8 warps; warp = 32 lanes at FIXED co (weight loads span
// <=2 cache lines, read ~once); thread covers 4 batches; Z staged in smem.
// ---------------------------------------------------------------------------
__global__ __launch_bounds__(256) void k_mix(const float* __restrict__ w1r,
                                             const float* __restrict__ w1i,
                                             const float* __restrict__ w2r,
                                             const float* __restrict__ w2i) {
    __shared__ float2 sZ[4][32][32]; // [bl][ci][lane] 32 KB
    int blk = blockIdx.x;            // 256 blocks
    int kt  = blk & 31;
    int cog = (blk >> 5) & 3;
    int bh  = blk >> 7;
    int tid = threadIdx.x;

    for (int i = tid; i < 4096; i += 256) {
        int lane = i & 31, ci = (i >> 5) & 31, bl = i >> 10;
        int b = bh * 4 + bl;
        sZ[bl][ci][lane] = g_Z[((size_t)(b * 32 + ci) * 32 + kt) * 32 + lane];
    }
    __syncthreads();

    int warp = tid >> 5, lane = tid & 31;
    int co = cog * 8 + warp;
    int kx = lane >> 1, z = lane & 1;
    const float* wr = (kt < 16) ? w1r : w2r;
    const float* wi = (kt < 16) ? w1i : w2i;
    int j = kt & 15;
    int wbase = co * 768 + j * 48 + kx * 3 + z; // + ci*24576

    float ar[4] = {0, 0, 0, 0}, ai[4] = {0, 0, 0, 0};
#pragma unroll 4
    for (int ci = 0; ci < 32; ci++) {
        float wre = wr[wbase + ci * 24576];
        float wim = wi[wbase + ci * 24576];
#pragma unroll
        for (int bl = 0; bl < 4; bl++) {
            float2 zv = sZ[bl][ci][lane];
            ar[bl] = fmaf(zv.x, wre, ar[bl]); ar[bl] = fmaf(-zv.y, wim, ar[bl]);
            ai[bl] = fmaf(zv.x, wim, ai[bl]); ai[bl] = fmaf(zv.y, wre, ai[bl]);
        }
    }
#pragma unroll
    for (int bl = 0; bl < 4; bl++) {
        int b = bh * 4 + bl;
        g_H[((size_t)(b * 32 + co) * 32 + kt) * 32 + lane] = make_float2(ar[bl], ai[bl]);
    }
}

// ---------------------------------------------------------------------------
// K4: inverse t-DFT with t/t+64 parity symmetry, smem-staged.
// Block = (slab, t0-group of 8): 8 KB H-slab + 4 KB twiddle rows; warp = one
// t0; per iter LDS.64 data + broadcast LDS.128 twiddle + 2 FFMA2.
// ---------------------------------------------------------------------------
__global__ __launch_bounds__(256) void k_inv_t() {
    __shared__ __align__(16) u64    sH[1024]; // [kt][lane] 8 KB
    __shared__ __align__(16) float4 sT[256];  // [t0l][kt]  4 KB
    int blk  = blockIdx.x;       // 2048 blocks
    int slab = blk >> 3;         // b*32+co
    int tg   = blk & 7;
    int tid  = threadIdx.x;

    const float4* Hs = reinterpret_cast<const float4*>(g_H + (size_t)slab * 1024);
    float4* sH4 = reinterpret_cast<float4*>(sH);
    for (int i = tid; i < 512; i += 256) sH4[i] = Hs[i];
    sT[tid] = g_Ti[tg * 256 + tid]; // 256 float4 exactly
    __syncthreads();

    int warp = tid >> 5, lane = tid & 31;
    int t0 = tg * 8 + warp; // 0..63
    const ulonglong2* T = reinterpret_cast<const ulonglong2*>(sT + warp * 32);
    u64 U0 = 0ull, V0 = 0ull, U1 = 0ull, V1 = 0ull;
#pragma unroll
    for (int kt = 0; kt < 32; kt += 2) {
        u64 v0 = sH[kt * 32 + lane];
        ulonglong2 w0 = T[kt];
        U0 = fma2(v0, w0.x, U0); V0 = fma2(v0, w0.y, V0);
        u64 v1 = sH[(kt + 1) * 32 + lane];
        ulonglong2 w1 = T[kt + 1];
        U1 = fma2(v1, w1.x, U1); V1 = fma2(v1, w1.y, V1);
    }
    float a, bb, c, d;
    up2(U0, a, bb); up2(V0, c, d); float er = a - d, ei = c + bb;
    up2(U1, a, bb); up2(V1, c, d); float orr = a - d, oi = c + bb;
    size_t base = (size_t)slab * 128;
    g_A[(base + t0) * 32 + lane]      = make_float2(er + orr, ei + oi);
    g_A[(base + t0 + 64) * 32 + lane] = make_float2(er - orr, ei - oi);
}

// ---------------------------------------------------------------------------
// K5: inverse x-DFT + irfft(p=3) + store. (R8 chain version — known good.)
// ---------------------------------------------------------------------------
__global__ __launch_bounds__(256) void k_inv_x(float* __restrict__ out) {
    __shared__ __align__(16) float2 sA[128]; // 4 rows x 32 coeffs
    int tid = threadIdx.x;
    size_t row0 = (size_t)blockIdx.x * 4;
    if (tid < 128) sA[tid] = g_A[row0 * 32 + tid];
    __syncthreads();

    int rl = tid >> 6, x0 = tid & 63;
    const ulonglong2* Ap = reinterpret_cast<const ulonglong2*>(sA) + rl * 16;

    float sr, si; sincospif((float)x0 / 128.0f, &si, &sr); // e^{+2pi i x0/256}
    u64 spp = pk2(sr, sr), sqq = pk2(si, si), sqn = pk2(-si, -si);
    u64 wpp = pk2(1.0f, 1.0f), wqq = pk2(0.0f, 0.0f);
    u64 A0[4] = {0,0,0,0}, B0[4] = {0,0,0,0}, A1[4] = {0,0,0,0}, B1[4] = {0,0,0,0};
#pragma unroll
    for (int k = 0; k < 16; k++) {
        ulonglong2 q = Ap[k]; // (a0 | a1) for this kx, uniform per 64 threads
        int gI = k & 3;
        A0[gI] = fma2(q.x, wpp, A0[gI]); B0[gI] = fma2(q.x, wqq, B0[gI]);
        A1[gI] = fma2(q.y, wpp, A1[gI]); B1[gI] = fma2(q.y, wqq, B1[gI]);
        cstep(wpp, wqq, spp, sqq, sqn);
    }
    float S0r[4], S0i[4], S1r[4], S1i[4];
#pragma unroll
    for (int gi = 0; gi < 4; gi++) {
        float a, b2, c, d;
        up2(A0[gi], a, b2); up2(B0[gi], c, d); S0r[gi] = a - d; S0i[gi] = c + b2;
        up2(A1[gi], a, b2); up2(B1[gi], c, d); S1r[gi] = a - d; S1i[gi] = c + b2;
    }
    // radix-4 butterflies: S(d) = T0+T2 | T1+iT3 | T0-T2 | T1-iT3
    float T0r = S0r[0] + S0r[2], T1r = S0r[0] - S0r[2];
    float T2r = S0r[1] + S0r[3];
    float T3i = S0i[1] - S0i[3];
    float U0r = S1r[0] + S1r[2], U1r = S1r[0] - S1r[2];
    float U2r = S1r[1] + S1r[3], U3r = S1r[1] - S1r[3];
    float U0i = S1i[0] + S1i[2], U1i = S1i[0] - S1i[2];
    float U2i = S1i[1] + S1i[3], U3i = S1i[1] - S1i[3];

    float s0[4], s1r_[4], s1i_[4];
    s0[0] = T0r + T2r; s1r_[0] = U0r + U2r; s1i_[0] = U0i + U2i; // d=0
    s0[1] = T1r - T3i; s1r_[1] = U1r - U3i; s1i_[1] = U1i + U3r; // d=64
    s0[2] = T0r - T2r; s1r_[2] = U0r - U2r; s1i_[2] = U0i - U2i; // d=128
    s0[3] = T1r + T3i; s1r_[3] = U1r + U3i; s1i_[3] = U1i - U3r; // d=192

    const float inv = 1.0f / 98304.0f; // 1/(T*X*P)
    size_t rbase = (row0 + rl) * 256;
#pragma unroll
    for (int dd = 0; dd < 4; dd++) {
        int xx = x0 + 64 * dd;
        float S0 = s0[dd], R = s1r_[dd], I = s1i_[dd];
        float p0 = (S0 + 2.0f * R) * inv;
        float p1 = (S0 + 2.0f * (-0.5f * R - SQ3H * I)) * inv;
        float p2 = (S0 + 2.0f * (-0.5f * R + SQ3H * I)) * inv;
        size_t o = (rbase + xx) * 3;
        out[o + 0] = p0;
        out[o + 1] = p1;
        out[o + 2] = p2;
    }
}

// ---------------------------------------------------------------------------
extern "C" void kernel_launch(void* const* d_in, const int* in_sizes, int n_in,
                              void* d_out, int out_size) {
    const float* x   = (const float*)d_in[0];
    const float* w1r = (const float*)d_in[1];
    const float* w1i = (const float*)d_in[2];
    const float* w2r = (const float*)d_in[3];
    const float* w2i = (const float*)d_in[4];
    float* out = (float*)d_out;

    k_tw<<<24, 256>>>();                         // twiddle tables
    k_fwd_x<<<4096, 256>>>(x);                   // 8 rows/block
    k_fwd_t<<<1024, 128>>>();                    // slab x kt-quarter, smem-staged
    k_mix<<<256, 256>>>(w1r, w1i, w2r, w2i);     // kt x co-group x b-half
    k_inv_t<<<2048, 256>>>();                    // slab x t0-group, smem-staged
    k_inv_x<<<8192, 256>>>(out);                 // 4 rows/block
}

// round 17
// speedup vs baseline: 1.5625x; 1.0960x over previous
#include <cuda_runtime.h>

// Problem constants
//   x  : [B=8, Ci=32, T=128, X=256, P=3]  float32
//   w* : [Ci=32, Co=32, M1=16, M2=16, M3=3] float32
//   out: [B=8, Co=32, T=128, X=256, P=3]  float32
//
// Active spectral modes: kt in {0..15} (w1) and {112..127} (w2),
// kx in {0..15}, kz in {0,1}. lane = kx*2 + z packs the 32 (kx,z) pairs.

#define SQ3H 0.8660254037844386f  // sqrt(3)/2
#define RS2  0.70710678118654752f // sqrt(2)/2

typedef unsigned long long u64;

// ---- packed f32x2 helpers (FFMA2 path) ------------------------------------
__device__ __forceinline__ u64 pk2(float lo, float hi) {
    u64 r; asm("mov.b64 %0, {%1, %2};" : "=l"(r) : "f"(lo), "f"(hi)); return r;
}
__device__ __forceinline__ void up2(u64 v, float& lo, float& hi) {
    asm("mov.b64 {%0, %1}, %2;" : "=f"(lo), "=f"(hi) : "l"(v));
}
__device__ __forceinline__ u64 fma2(u64 a, u64 b, u64 c) {
    u64 d; asm("fma.rn.f32x2 %0, %1, %2, %3;" : "=l"(d) : "l"(a), "l"(b), "l"(c)); return d;
}
__device__ __forceinline__ u64 mul2(u64 a, u64 b) {
    u64 d; asm("mul.rn.f32x2 %0, %1, %2;" : "=l"(d) : "l"(a), "l"(b)); return d;
}
// dup-packed complex twiddle chain step: w *= s  (both halves identical dups)
__device__ __forceinline__ void cstep(u64& wpp, u64& wqq, u64 spp, u64 sqq, u64 sqn) {
    u64 t1 = mul2(wqq, sqn);          // -wi*si
    u64 np = fma2(wpp, spp, t1);      // wr' = wr*sr - wi*si
    u64 t2 = mul2(wqq, spp);          //  wi*sr
    wqq    = fma2(wpp, sqq, t2);      // wi' = wr*si + wi*sr
    wpp    = np;
}

// Scratch (device globals; allocation is banned)
static __device__ __align__(16) float2 g_Y[8 * 32 * 128 * 32];   // [slab=b*32+ci][t][lane]  8 MB
static __device__ __align__(16) float2 g_Z[8 * 32 * 32 * 32];    // [b][ci][kt][lane]        2 MB
static __device__ __align__(16) float2 g_Hp0[8 * 32 * 32 * 32];  // ci-half-0 partial        2 MB
static __device__ __align__(16) float2 g_Hp1[8 * 32 * 32 * 32];  // ci-half-1 partial        2 MB
static __device__ __align__(16) float2 g_A[8 * 32 * 128 * 32];   // [b][co][t][lane]         8 MB

// ---------------------------------------------------------------------------
// K1: forward p-rfft + x-DFT, radix-8 DIF over x.
// Block = 8 rows (256 thr). Phase 1: thread = (row, x0<32); length-3 p-rfft on
// 8 samples x0+32j, then 8-point DFT over j -> classes D_r (r = k mod 8) for
// both channels (f0 real: D7=conj(D1), D5=conj(D3) exploited).
// Phase 2: warp = row, lane = (kx,z); 32-step dup-packed chain, quadrature
// accumulation. sD padded to 17 slots to keep stores 2-way-conflict max.
// ---------------------------------------------------------------------------
__global__ __launch_bounds__(256) void k_fwd_x(const float* __restrict__ x) {
    __shared__ __align__(16) float2 sD[8][32][17]; // ~34 KB
    int row0 = blockIdx.x * 8;
    int tid = threadIdx.x;
    int rl = tid >> 5, x0 = tid & 31;

    const float* xp = x + (size_t)(row0 + rl) * 768 + 3 * x0;
    float f0[8], f1r[8], f1i[8];
#pragma unroll
    for (int j = 0; j < 8; j++) {
        float a = xp[96 * j + 0], b = xp[96 * j + 1], c = xp[96 * j + 2];
        float s = b + c;
        f0[j]  = a + s;
        f1r[j] = fmaf(-0.5f, s, a);
        f1i[j] = SQ3H * (c - b);
    }
    float2* d = sD[rl][x0];
    // ---- f0 (real) channel: 8-pt DFT with real-input symmetry ----
    {
        float pe0 = f0[0] + f0[4], me0 = f0[0] - f0[4];
        float pe1 = f0[2] + f0[6], me1 = f0[2] - f0[6];
        float po0 = f0[1] + f0[5], mo0 = f0[1] - f0[5];
        float po1 = f0[3] + f0[7], mo1 = f0[3] - f0[7];
        float E0 = pe0 + pe1, E2 = pe0 - pe1;
        float O0 = po0 + po1, O2 = po0 - po1;
        float t1 = RS2 * (mo0 - mo1);
        float t2 = RS2 * (mo0 + mo1);
        d[0] = make_float2(E0 + O0, 0.0f);
        d[4] = make_float2(E0 - O0, 0.0f);
        d[2] = make_float2(E2, -O2);
        d[6] = make_float2(E2,  O2);
        d[1] = make_float2(me0 + t1, -me1 - t2);
        d[5] = make_float2(me0 - t1, -me1 + t2);
        d[3] = make_float2(me0 - t1,  me1 - t2);
        d[7] = make_float2(me0 + t1,  me1 + t2);
    }
    // ---- f1 (complex) channel: full 8-pt DFT ----
    {
        float pe0r = f1r[0] + f1r[4], pe0i = f1i[0] + f1i[4];
        float me0r = f1r[0] - f1r[4], me0i = f1i[0] - f1i[4];
        float pe1r = f1r[2] + f1r[6], pe1i = f1i[2] + f1i[6];
        float me1r = f1r[2] - f1r[6], me1i = f1i[2] - f1i[6];
        float po0r = f1r[1] + f1r[5], po0i = f1i[1] + f1i[5];
        float mo0r = f1r[1] - f1r[5], mo0i = f1i[1] - f1i[5];
        float po1r = f1r[3] + f1r[7], po1i = f1i[3] + f1i[7];
        float mo1r = f1r[3] - f1r[7], mo1i = f1i[3] - f1i[7];
        float E0r = pe0r + pe1r, E0i = pe0i + pe1i;
        float E2r = pe0r - pe1r, E2i = pe0i - pe1i;
        float E1r = me0r + me1i, E1i = me0i - me1r;  // me0 - i*me1
        float E3r = me0r - me1i, E3i = me0i + me1r;  // me0 + i*me1
        float O0r = po0r + po1r, O0i = po0i + po1i;
        float O2r = po0r - po1r, O2i = po0i - po1i;
        float O1r = mo0r + mo1i, O1i = mo0i - mo1r;
        float O3r = mo0r - mo1i, O3i = mo0i + mo1r;
        float W1r = RS2 * (O1r + O1i), W1i = RS2 * (O1i - O1r); // e^{-i pi/4} * O1
        float W2r = O2i,               W2i = -O2r;              // -i * O2
        float W3r = RS2 * (O3i - O3r), W3i = -RS2 * (O3r + O3i);// e^{-3i pi/4} * O3
        d[8]  = make_float2(E0r + O0r, E0i + O0i);
        d[12] = make_float2(E0r - O0r, E0i - O0i);
        d[9]  = make_float2(E1r + W1r, E1i + W1i);
        d[13] = make_float2(E1r - W1r, E1i - W1i);
        d[10] = make_float2(E2r + W2r, E2i + W2i);
        d[14] = make_float2(E2r - W2r, E2i - W2i);
        d[11] = make_float2(E3r + W3r, E3i + W3i);
        d[15] = make_float2(E3r - W3r, E3i - W3i);
    }
    __syncthreads();

    // ---- phase 2: 32-step chain per (kx,z) lane ----
    int warp = tid >> 5, lane = tid & 31;
    int kx = lane >> 1, z = lane & 1;
    int slot = (z << 3) | (kx & 7);

    float sr, si; sincospif(-(float)kx / 128.0f, &si, &sr); // e^{-2pi i kx/256}
    u64 spp = pk2(sr, sr), sqq = pk2(si, si), sqn = pk2(-si, -si);
    u64 wpp = pk2(1.0f, 1.0f), wqq = pk2(0.0f, 0.0f);
    u64 U = 0ull, V = 0ull;
    const u64* dp = reinterpret_cast<const u64*>(&sD[warp][0][slot]);
#pragma unroll 8
    for (int xq = 0; xq < 32; xq++) {
        u64 v = dp[xq * 17];
        U = fma2(v, wpp, U);
        V = fma2(v, wqq, V);
        cstep(wpp, wqq, spp, sqq, sqn);
    }
    float ua, ub, va, vb; up2(U, ua, ub); up2(V, va, vb);
    g_Y[(size_t)(row0 + warp) * 32 + lane] = make_float2(ua - vb, va + ub);
}

// ---------------------------------------------------------------------------
// K2: forward t-DFT: 128 t -> 32 kt, smem-staged; twiddles computed in-block
// (no global table, no k_tw launch). Block (128 thr) = slab x kt-quarter.
// ---------------------------------------------------------------------------
__global__ __launch_bounds__(128) void k_fwd_t() {
    __shared__ __align__(16) u64    sY[4096]; // [t][lane] 32 KB
    __shared__ __align__(16) float4 sT[1024]; // [ktl][t]  16 KB
    int blk  = blockIdx.x;       // 1024 blocks
    int slab = blk >> 2;         // b*32+ci
    int kq   = blk & 3;          // kt quarter
    int tid  = threadIdx.x;

    const float4* Ys = reinterpret_cast<const float4*>(g_Y + (size_t)slab * 4096);
    float4* sY4 = reinterpret_cast<float4*>(sY);
#pragma unroll
    for (int i = tid; i < 2048; i += 128) sY4[i] = Ys[i];
#pragma unroll
    for (int i = tid; i < 1024; i += 128) {
        int ktl = i >> 7, t = i & 127;
        int kt = kq * 8 + ktl;
        int f = (kt < 16) ? kt : 96 + kt;
        float s, c; sincospif(-(float)(f * t) / 64.0f, &s, &c);
        sT[i] = make_float4(c, c, s, s);
    }
    __syncthreads();

    int warp = tid >> 5, lane = tid & 31;
    int k0 = 2 * warp, k1 = 2 * warp + 1; // local kt within quarter
    const ulonglong2* T0 = reinterpret_cast<const ulonglong2*>(sT + k0 * 128);
    const ulonglong2* T1 = reinterpret_cast<const ulonglong2*>(sT + k1 * 128);
    u64 U0 = 0ull, V0 = 0ull, U1 = 0ull, V1 = 0ull;
#pragma unroll 8
    for (int t = 0; t < 128; t++) {
        u64 v = sY[t * 32 + lane];
        ulonglong2 w0 = T0[t]; // (c,c | s,s), broadcast
        U0 = fma2(v, w0.x, U0); V0 = fma2(v, w0.y, V0);
        ulonglong2 w1 = T1[t];
        U1 = fma2(v, w1.x, U1); V1 = fma2(v, w1.y, V1);
    }
    float a, b2, c, d;
    up2(U0, a, b2); up2(V0, c, d);
    g_Z[((size_t)slab * 32 + kq * 8 + k0) * 32 + lane] = make_float2(a - d, c + b2);
    up2(U1, a, b2); up2(V1, c, d);
    g_Z[((size_t)slab * 32 + kq * 8 + k1) * 32 + lane] = make_float2(a - d, c + b2);
}

// ---------------------------------------------------------------------------
// K3: channel mix, reuse-tiled + ci-split for occupancy.
// Grid = kt(32) x cog(8) x bh(2) x cih(2) = 1024 blocks of 128 thr.
// Warp = fixed co (coalesced weight reads); thread covers 4 batches;
// 16-ci half-sum -> partial H buffer; K4 adds the halves.
// ---------------------------------------------------------------------------
__global__ __launch_bounds__(128) void k_mix(const float* __restrict__ w1r,
                                             const float* __restrict__ w1i,
                                             const float* __restrict__ w2r,
                                             const float* __restrict__ w2i) {
    __shared__ float2 sZ[4][16][32]; // [bl][cil][lane] 16 KB
    int blk = blockIdx.x;            // 1024 blocks
    int kt  = blk & 31;
    int cog = (blk >> 5) & 7;
    int bh  = (blk >> 8) & 1;
    int cih = blk >> 9;
    int tid = threadIdx.x;

    for (int i = tid; i < 2048; i += 128) {
        int lane = i & 31, cil = (i >> 5) & 15, bl = i >> 9;
        int b = bh * 4 + bl, ci = cih * 16 + cil;
        sZ[bl][cil][lane] = g_Z[((size_t)(b * 32 + ci) * 32 + kt) * 32 + lane];
    }
    __syncthreads();

    int warp = tid >> 5, lane = tid & 31;
    int co = cog * 4 + warp;
    int kx = lane >> 1, z = lane & 1;
    const float* wr = (kt < 16) ? w1r : w2r;
    const float* wi = (kt < 16) ? w1i : w2i;
    int j = kt & 15;
    int wb = co * 768 + j * 48 + kx * 3 + z + cih * 16 * 24576; // + cil*24576

    float ar[4] = {0, 0, 0, 0}, ai[4] = {0, 0, 0, 0};
#pragma unroll 4
    for (int cil = 0; cil < 16; cil++) {
        float wre = wr[wb + cil * 24576];
        float wim = wi[wb + cil * 24576];
#pragma unroll
        for (int bl = 0; bl < 4; bl++) {
            float2 zv = sZ[bl][cil][lane];
            ar[bl] = fmaf(zv.x, wre, ar[bl]); ar[bl] = fmaf(-zv.y, wim, ar[bl]);
            ai[bl] = fmaf(zv.x, wim, ai[bl]); ai[bl] = fmaf(zv.y, wre, ai[bl]);
        }
    }
    float2* Hp = cih ? g_Hp1 : g_Hp0;
#pragma unroll
    for (int bl = 0; bl < 4; bl++) {
        int b = bh * 4 + bl;
        Hp[((size_t)(b * 32 + co) * 32 + kt) * 32 + lane] = make_float2(ar[bl], ai[bl]);
    }
}

// ---------------------------------------------------------------------------
// K4: inverse t-DFT with t/t+64 parity symmetry, smem-staged.
// Stages sH = Hp0 + Hp1 (completes the ci-split reduction for free);
// twiddles computed in-block. Block = (slab, t0-group of 8).
// ---------------------------------------------------------------------------
__global__ __launch_bounds__(256) void k_inv_t() {
    __shared__ __align__(16) u64    sH[1024]; // [kt][lane] 8 KB
    __shared__ __align__(16) float4 sT[256];  // [t0l][kt]  4 KB
    int blk  = blockIdx.x;       // 2048 blocks
    int slab = blk >> 3;         // b*32+co
    int tg   = blk & 7;
    int tid  = threadIdx.x;

    const float4* H0 = reinterpret_cast<const float4*>(g_Hp0 + (size_t)slab * 1024);
    const float4* H1 = reinterpret_cast<const float4*>(g_Hp1 + (size_t)slab * 1024);
    float4* sH4 = reinterpret_cast<float4*>(sH);
    for (int i = tid; i < 512; i += 256) {
        float4 a = H0[i], b = H1[i];
        sH4[i] = make_float4(a.x + b.x, a.y + b.y, a.z + b.z, a.w + b.w);
    }
    {
        int t0l = tid >> 5, kt = tid & 31;
        int t0 = tg * 8 + t0l;
        int f = (kt < 16) ? kt : 96 + kt;
        float s, c; sincospif((float)(f * t0) / 64.0f, &s, &c);
        sT[tid] = make_float4(c, c, s, s);
    }
    __syncthreads();

    int warp = tid >> 5, lane = tid & 31;
    int t0 = tg * 8 + warp; // 0..63
    const ulonglong2* T = reinterpret_cast<const ulonglong2*>(sT + warp * 32);
    u64 U0 = 0ull, V0 = 0ull, U1 = 0ull, V1 = 0ull;
#pragma unroll
    for (int kt = 0; kt < 32; kt += 2) {
        u64 v0 = sH[kt * 32 + lane];
        ulonglong2 w0 = T[kt];
        U0 = fma2(v0, w0.x, U0); V0 = fma2(v0, w0.y, V0);
        u64 v1 = sH[(kt + 1) * 32 + lane];
        ulonglong2 w1 = T[kt + 1];
        U1 = fma2(v1, w1.x, U1); V1 = fma2(v1, w1.y, V1);
    }
    float a, bb, c, d;
    up2(U0, a, bb); up2(V0, c, d); float er = a - d, ei = c + bb;
    up2(U1, a, bb); up2(V1, c, d); float orr = a - d, oi = c + bb;
    size_t base = (size_t)slab * 128;
    g_A[(base + t0) * 32 + lane]      = make_float2(er + orr, ei + oi);
    g_A[(base + t0 + 64) * 32 + lane] = make_float2(er - orr, ei - oi);
}

// ---------------------------------------------------------------------------
// K5: inverse x-DFT + irfft(p=3) + store. (R14 version — known good.)
// ---------------------------------------------------------------------------
__global__ __launch_bounds__(256) void k_inv_x(float* __restrict__ out) {
    __shared__ __align__(16) float2 sA[128]; // 4 rows x 32 coeffs
    int tid = threadIdx.x;
    size_t row0 = (size_t)blockIdx.x * 4;
    if (tid < 128) sA[tid] = g_A[row0 * 32 + tid];
    __syncthreads();

    int rl = tid >> 6, x0 = tid & 63;
    const ulonglong2* Ap = reinterpret_cast<const ulonglong2*>(sA) + rl * 16;

    float sr, si; sincospif((float)x0 / 128.0f, &si, &sr); // e^{+2pi i x0/256}
    u64 spp = pk2(sr, sr), sqq = pk2(si, si), sqn = pk2(-si, -si);
    u64 wpp = pk2(1.0f, 1.0f), wqq = pk2(0.0f, 0.0f);
    u64 A0[4] = {0,0,0,0}, B0[4] = {0,0,0,0}, A1[4] = {0,0,0,0}, B1[4] = {0,0,0,0};
#pragma unroll
    for (int k = 0; k < 16; k++) {
        ulonglong2 q = Ap[k]; // (a0 | a1) for this kx, uniform per 64 threads
        int gI = k & 3;
        A0[gI] = fma2(q.x, wpp, A0[gI]); B0[gI] = fma2(q.x, wqq, B0[gI]);
        A1[gI] = fma2(q.y, wpp, A1[gI]); B1[gI] = fma2(q.y, wqq, B1[gI]);
        cstep(wpp, wqq, spp, sqq, sqn);
    }
    float S0r[4], S0i[4], S1r[4], S1i[4];
#pragma unroll
    for (int gi = 0; gi < 4; gi++) {
        float a, b2, c, d;
        up2(A0[gi], a, b2); up2(B0[gi], c, d); S0r[gi] = a - d; S0i[gi] = c + b2;
        up2(A1[gi], a, b2); up2(B1[gi], c, d); S1r[gi] = a - d; S1i[gi] = c + b2;
    }
    // radix-4 butterflies: S(d) = T0+T2 | T1+iT3 | T0-T2 | T1-iT3
    float T0r = S0r[0] + S0r[2], T1r = S0r[0] - S0r[2];
    float T2r = S0r[1] + S0r[3];
    float T3i = S0i[1] - S0i[3];
    float U0r = S1r[0] + S1r[2], U1r = S1r[0] - S1r[2];
    float U2r = S1r[1] + S1r[3], U3r = S1r[1] - S1r[3];
    float U0i = S1i[0] + S1i[2], U1i = S1i[0] - S1i[2];
    float U2i = S1i[1] + S1i[3], U3i = S1i[1] - S1i[3];

    float s0[4], s1r_[4], s1i_[4];
    s0[0] = T0r + T2r; s1r_[0] = U0r + U2r; s1i_[0] = U0i + U2i; // d=0
    s0[1] = T1r - T3i; s1r_[1] = U1r - U3i; s1i_[1] = U1i + U3r; // d=64
    s0[2] = T0r - T2r; s1r_[2] = U0r - U2r; s1i_[2] = U0i - U2i; // d=128
    s0[3] = T1r + T3i; s1r_[3] = U1r + U3i; s1i_[3] = U1i - U3r; // d=192

    const float inv = 1.0f / 98304.0f; // 1/(T*X*P)
    size_t rbase = (row0 + rl) * 256;
#pragma unroll
    for (int dd = 0; dd < 4; dd++) {
        int xx = x0 + 64 * dd;
        float S0 = s0[dd], R = s1r_[dd], I = s1i_[dd];
        float p0 = (S0 + 2.0f * R) * inv;
        float p1 = (S0 + 2.0f * (-0.5f * R - SQ3H * I)) * inv;
        float p2 = (S0 + 2.0f * (-0.5f * R + SQ3H * I)) * inv;
        size_t o = (rbase + xx) * 3;
        out[o + 0] = p0;
        out[o + 1] = p1;
        out[o + 2] = p2;
    }
}

// ---------------------------------------------------------------------------
extern "C" void kernel_launch(void* const* d_in, const int* in_sizes, int n_in,
                              void* d_out, int out_size) {
    const float* x   = (const float*)d_in[0];
    const float* w1r = (const float*)d_in[1];
    const float* w1i = (const float*)d_in[2];
    const float* w2r = (const float*)d_in[3];
    const float* w2i = (const float*)d_in[4];
    float* out = (float*)d_out;

    k_fwd_x<<<4096, 256>>>(x);                   // radix-8, 8 rows/block
    k_fwd_t<<<1024, 128>>>();                    // slab x kt-quarter, smem-staged
    k_mix<<<1024, 128>>>(w1r, w1i, w2r, w2i);    // kt x cog x bh x ci-half
    k_inv_t<<<2048, 256>>>();                    // sums ci-halves + inv-t
    k_inv_x<<<8192, 256>>>(out);                 // 4 rows/block
}